// round 2
// baseline (speedup 1.0000x reference)
#include <cuda_runtime.h>
#include <math.h>

#define NPTS 262144
#define NP 10
#define NL 16
#define TSZ (1u << 19)
#define PTS_PER_BLOCK 16
#define THREADS 128

// shared layout (floats): wih_t[32][192] | whh_t[64][192] | wfc[64] | gs[16] | emb[16][10][32] | anc[16][10]
#define SM_WIH   0
#define SM_WHH   6144
#define SM_WFC   (6144 + 12288)
#define SM_GS    (SM_WFC + 64)
#define SM_EMB   (SM_GS + 16)
#define SM_ANC   (SM_EMB + 5120)
#define SM_TOTAL (SM_ANC + 160)
#define SMEM_BYTES (SM_TOTAL * 4)

struct ResParams { float gs[NL]; };

__device__ __forceinline__ float sigm(float x) { return 1.0f / (1.0f + __expf(-x)); }

__global__ __launch_bounds__(THREADS)
void xyz_tpc_kernel(const float* __restrict__ xyzt,
                    const float2* __restrict__ tab,
                    const float* __restrict__ w_ih,
                    const float* __restrict__ w_hh,
                    const float* __restrict__ w_fc,
                    float* __restrict__ out,
                    ResParams rp)
{
    extern __shared__ float sm[];
    float* wih_sh = sm + SM_WIH;
    float* whh_sh = sm + SM_WHH;
    float* wfc_sh = sm + SM_WFC;
    float* gs_sh  = sm + SM_GS;
    float* emb_sh = sm + SM_EMB;
    float* anc_sh = sm + SM_ANC;

    const int tid = threadIdx.x;

    // stage weights transposed: wih_sh[d*192 + g] = w_ih[g*32 + d]
    for (int i = tid; i < 6144; i += THREADS) {
        int g = i >> 5, d = i & 31;
        wih_sh[d * 192 + g] = w_ih[i];
    }
    for (int i = tid; i < 12288; i += THREADS) {
        int g = i >> 6, k = i & 63;
        whh_sh[k * 192 + g] = w_hh[i];
    }
    if (tid < 64) wfc_sh[tid] = w_fc[tid];
    if (tid < 16) gs_sh[tid] = rp.gs[tid];
    __syncthreads();

    const int lane  = tid & 31;
    const int wrp   = tid >> 5;
    const int pbase = wrp * 4;                                   // warp's point base within block
    const int gpt   = blockIdx.x * PTS_PER_BLOCK + pbase;        // global point base

    // load the warp's 4 points (broadcast LDG.128)
    float4 pt[4];
    #pragma unroll
    for (int q = 0; q < 4; ++q)
        pt[q] = reinterpret_cast<const float4*>(xyzt)[gpt + q];

    // ---------------- Phase 1: hash-grid gather + trilinear ----------------
    // lane <-> (level_sub, corner): 4 levels x 8 corners per pass, 4 passes
    const int lsub = lane >> 3;
    const int c    = lane & 7;
    const int oi = (c >> 2) & 1, oj = (c >> 1) & 1, ok = c & 1;

    #pragma unroll
    for (int g = 0; g < 4; ++g) {
        const int l = g * 4 + lsub;
        const float gsv = gs_sh[l];
        const float2* tl = tab + (size_t)l * TSZ;
        #pragma unroll
        for (int q = 0; q < 4; ++q) {
            float x = fminf(fmaxf(pt[q].x, -1.0f), 1.0f);
            float y = fminf(fmaxf(pt[q].y, -1.0f), 1.0f);
            float z = fminf(fmaxf(pt[q].z, -1.0f), 1.0f);
            float tx = __fdiv_rn(x + 1.0f, gsv);
            float ty = __fdiv_rn(y + 1.0f, gsv);
            float tz = __fdiv_rn(z + 1.0f, gsv);
            float bx = floorf(tx), by = floorf(ty), bz = floorf(tz);
            int ibx = (int)bx, iby = (int)by, ibz = (int)bz;
            float wx = __fdiv_rn(x - (bx * gsv - 1.0f), gsv);
            float wy = __fdiv_rn(y - (by * gsv - 1.0f), gsv);
            float wz = __fdiv_rn(z - (bz * gsv - 1.0f), gsv);

            unsigned cx = (unsigned)(ibx + oi);
            unsigned cy = (unsigned)(iby + oj);
            unsigned cz = (unsigned)(ibz + ok);
            unsigned hidx = (cx ^ (cy * 2654435761u) ^ (cz * 805459861u)) & (TSZ - 1u);

            float wc = (oi ? wx : 1.0f - wx) * (oj ? wy : 1.0f - wy) * (ok ? wz : 1.0f - wz);

            const float2* src = tl + hidx;
            float sx[NP], sy[NP];
            #pragma unroll
            for (int p = 0; p < NP; ++p) {
                float2 v = __ldg(src + (size_t)p * (size_t)(NL * (size_t)TSZ));
                sx[p] = wc * v.x;
                sy[p] = wc * v.y;
            }
            // reduce over 8 corners (butterfly within 8-lane groups)
            #pragma unroll
            for (int m = 1; m < 8; m <<= 1) {
                #pragma unroll
                for (int p = 0; p < NP; ++p) {
                    sx[p] += __shfl_xor_sync(0xffffffffu, sx[p], m);
                    sy[p] += __shfl_xor_sync(0xffffffffu, sy[p], m);
                }
            }
            if (c == 0) {
                float* e = emb_sh + (pbase + q) * (NP * 32) + 2 * l;
                #pragma unroll
                for (int p = 0; p < NP; ++p) {
                    e[p * 32]     = sx[p];
                    e[p * 32 + 1] = sy[p];
                }
            }
        }
    }
    __syncwarp();

    // ---------------- Phase 2: GRU over pieces ----------------
    // lane owns rows {lane + 32*i, i=0..5} of the 192 gate pre-activations.
    float h0[4] = {0, 0, 0, 0}, h1[4] = {0, 0, 0, 0};
    float anc[4] = {0, 0, 0, 0};

    for (int p = 0; p < NP; ++p) {
        float ar0[4] = {0,0,0,0}, ar1[4] = {0,0,0,0};
        float az0[4] = {0,0,0,0}, az1[4] = {0,0,0,0};
        float ai0[4] = {0,0,0,0}, ai1[4] = {0,0,0,0};
        float an0[4] = {0,0,0,0}, an1[4] = {0,0,0,0};

        // gi = w_ih @ emb_p
        #pragma unroll 4
        for (int d = 0; d < 32; ++d) {
            const float* wr = wih_sh + d * 192;
            float w0 = wr[lane],        w1 = wr[lane + 32];
            float w2 = wr[lane + 64],   w3 = wr[lane + 96];
            float w4 = wr[lane + 128],  w5 = wr[lane + 160];
            #pragma unroll
            for (int q = 0; q < 4; ++q) {
                float e = emb_sh[((pbase + q) * NP + p) * 32 + d];
                ar0[q] += w0 * e; ar1[q] += w1 * e;
                az0[q] += w2 * e; az1[q] += w3 * e;
                ai0[q] += w4 * e; ai1[q] += w5 * e;
            }
        }
        // gh = w_hh @ h  (skip at p==0, h==0)
        if (p > 0) {
            #pragma unroll 4
            for (int k = 0; k < 32; ++k) {
                const float* wr = whh_sh + k * 192;
                float w0 = wr[lane],        w1 = wr[lane + 32];
                float w2 = wr[lane + 64],   w3 = wr[lane + 96];
                float w4 = wr[lane + 128],  w5 = wr[lane + 160];
                #pragma unroll
                for (int q = 0; q < 4; ++q) {
                    float hk = __shfl_sync(0xffffffffu, h0[q], k);
                    ar0[q] += w0 * hk; ar1[q] += w1 * hk;
                    az0[q] += w2 * hk; az1[q] += w3 * hk;
                    an0[q] += w4 * hk; an1[q] += w5 * hk;
                }
            }
            #pragma unroll 4
            for (int k = 0; k < 32; ++k) {
                const float* wr = whh_sh + (k + 32) * 192;
                float w0 = wr[lane],        w1 = wr[lane + 32];
                float w2 = wr[lane + 64],   w3 = wr[lane + 96];
                float w4 = wr[lane + 128],  w5 = wr[lane + 160];
                #pragma unroll
                for (int q = 0; q < 4; ++q) {
                    float hk = __shfl_sync(0xffffffffu, h1[q], k);
                    ar0[q] += w0 * hk; ar1[q] += w1 * hk;
                    az0[q] += w2 * hk; az1[q] += w3 * hk;
                    an0[q] += w4 * hk; an1[q] += w5 * hk;
                }
            }
        }
        // gates + h update + delta reduction
        #pragma unroll
        for (int q = 0; q < 4; ++q) {
            float r0 = sigm(ar0[q]), r1 = sigm(ar1[q]);
            float z0 = sigm(az0[q]), z1 = sigm(az1[q]);
            float n0 = tanhf(ai0[q] + r0 * an0[q]);
            float n1 = tanhf(ai1[q] + r1 * an1[q]);
            h0[q] = (1.0f - z0) * n0 + z0 * h0[q];
            h1[q] = (1.0f - z1) * n1 + z1 * h1[q];

            float part = h0[q] * wfc_sh[lane] + h1[q] * wfc_sh[lane + 32];
            #pragma unroll
            for (int m = 16; m >= 1; m >>= 1)
                part += __shfl_xor_sync(0xffffffffu, part, m);
            anc[q] += __fdiv_rn(part * 2.0f, 10.0f);   // delta * 2 * (T_MAX-T_MIN) / N_PIECES, cumsum
            if (lane == 0) anc_sh[(pbase + q) * NP + p] = anc[q];
        }
    }
    __syncwarp();

    // ---------------- Phase 3: softmax weights + output ----------------
    #pragma unroll
    for (int q = 0; q < 4; ++q) {
        float t = pt[q].w;
        float lg[NP];
        float mx = -1e30f;
        #pragma unroll
        for (int p = 0; p < NP; ++p) {
            float a = anc_sh[(pbase + q) * NP + p];
            float L = -__fdiv_rn(fabsf(t - a), 100.0f);
            lg[p] = L;
            mx = fmaxf(mx, L);
        }
        float s = 0.0f, o = 0.0f;
        #pragma unroll
        for (int p = 0; p < NP; ++p) {
            float w = __expf(lg[p] - mx);
            s += w;
            o += w * emb_sh[((pbase + q) * NP + p) * 32 + lane];
        }
        out[(size_t)(gpt + q) * 32 + lane] = __fdiv_rn(o, s);
    }
}

extern "C" void kernel_launch(void* const* d_in, const int* in_sizes, int n_in,
                              void* d_out, int out_size)
{
    const float*  xyzt = (const float*)d_in[0];
    const float2* tab  = (const float2*)d_in[1];
    const float*  w_ih = (const float*)d_in[2];
    const float*  w_hh = (const float*)d_in[3];
    const float*  w_fc = (const float*)d_in[4];
    float* out = (float*)d_out;

    // Replicate numpy's RESOLUTIONS computation with the same host libm:
    // B = exp((log(4096)-log(128))/15); res_l = floor(128 * B**l); gs = 2/res (f32 div)
    ResParams rp;
    double B = exp((log(4096.0) - log(128.0)) / 15.0);
    for (int l = 0; l < NL; ++l) {
        double v = floor(128.0 * pow(B, (double)l));
        rp.gs[l] = 2.0f / (float)v;
    }

    cudaFuncSetAttribute(xyz_tpc_kernel, cudaFuncAttributeMaxDynamicSharedMemorySize, SMEM_BYTES);

    dim3 grid(NPTS / PTS_PER_BLOCK);
    xyz_tpc_kernel<<<grid, THREADS, SMEM_BYTES>>>(xyzt, tab, w_ih, w_hh, w_fc, out, rp);
}

// round 3
// speedup vs baseline: 1.1212x; 1.1212x over previous
#include <cuda_runtime.h>
#include <cuda_bf16.h>
#include <math.h>

#define NPTS 262144
#define NP 10
#define NL 16
#define TSZ (1u << 19)
#define PTS_PER_BLOCK 48
#define THREADS 384

// shared layout (float units):
// wih2[32*96] bf162 | whh2[64*96] bf162 | wfc[64] | gs[16] | emb[48][10][32] | anc[48][10]
#define SM_WIH2  0
#define SM_WHH2  3072
#define SM_WFC   9216
#define SM_GS    9280
#define SM_EMB   9296
#define SM_ANC   (9296 + 48 * 320)
#define SM_TOTAL (SM_ANC + 480)
#define SMEM_BYTES (SM_TOTAL * 4)

struct ResParams { float gs[NL]; };

__device__ __forceinline__ float sigm(float x) { return 1.0f / (1.0f + __expf(-x)); }

__global__ __launch_bounds__(THREADS, 2)
void xyz_tpc_kernel(const float* __restrict__ xyzt,
                    const float2* __restrict__ tab,
                    const float* __restrict__ w_ih,
                    const float* __restrict__ w_hh,
                    const float* __restrict__ w_fc,
                    float* __restrict__ out,
                    ResParams rp)
{
    extern __shared__ float sm[];
    __nv_bfloat162* wih2 = reinterpret_cast<__nv_bfloat162*>(sm + SM_WIH2);
    __nv_bfloat162* whh2 = reinterpret_cast<__nv_bfloat162*>(sm + SM_WHH2);
    float* wfc_sh = sm + SM_WFC;
    float* gs_sh  = sm + SM_GS;
    float* emb_sh = sm + SM_EMB;
    float* anc_sh = sm + SM_ANC;

    const int tid = threadIdx.x;

    // stage weights as bf16 pairs: pair j for output rows (ln + 64j, ln + 64j + 32)
    for (int i = tid; i < 32 * 96; i += THREADS) {
        int d = i / 96, r = i % 96;
        int j = r >> 5, ln = r & 31;
        float a = w_ih[(ln + 64 * j) * 32 + d];
        float b = w_ih[(ln + 64 * j + 32) * 32 + d];
        wih2[i] = __floats2bfloat162_rn(a, b);
    }
    for (int i = tid; i < 64 * 96; i += THREADS) {
        int k = i / 96, r = i % 96;
        int j = r >> 5, ln = r & 31;
        float a = w_hh[(ln + 64 * j) * 64 + k];
        float b = w_hh[(ln + 64 * j + 32) * 64 + k];
        whh2[i] = __floats2bfloat162_rn(a, b);
    }
    if (tid < 64) wfc_sh[tid] = w_fc[tid];
    if (tid < 16) gs_sh[tid] = rp.gs[tid];
    __syncthreads();

    const int lane  = tid & 31;
    const int wrp   = tid >> 5;
    const int pbase = wrp * 4;
    const int gpt   = blockIdx.x * PTS_PER_BLOCK + pbase;

    if (gpt >= NPTS) return;   // warp-uniform (NPTS % 4pts == 0)

    // warp's 4 points
    float4 pt[4];
    #pragma unroll
    for (int q = 0; q < 4; ++q)
        pt[q] = reinterpret_cast<const float4*>(xyzt)[gpt + q];

    // ---------------- Phase 1: hash-grid gather + trilinear ----------------
    const int lsub = lane >> 3;
    const int c    = lane & 7;
    const int oi = (c >> 2) & 1, oj = (c >> 1) & 1, ok = c & 1;

    #pragma unroll
    for (int g = 0; g < 4; ++g) {
        const int l = g * 4 + lsub;
        const float gsv = gs_sh[l];
        const float2* tl = tab + (size_t)l * TSZ;
        #pragma unroll
        for (int q = 0; q < 4; ++q) {
            float x = fminf(fmaxf(pt[q].x, -1.0f), 1.0f);
            float y = fminf(fmaxf(pt[q].y, -1.0f), 1.0f);
            float z = fminf(fmaxf(pt[q].z, -1.0f), 1.0f);
            float tx = __fdiv_rn(x + 1.0f, gsv);
            float ty = __fdiv_rn(y + 1.0f, gsv);
            float tz = __fdiv_rn(z + 1.0f, gsv);
            float bx = floorf(tx), by = floorf(ty), bz = floorf(tz);
            int ibx = (int)bx, iby = (int)by, ibz = (int)bz;
            float wx = __fdiv_rn(x - (bx * gsv - 1.0f), gsv);
            float wy = __fdiv_rn(y - (by * gsv - 1.0f), gsv);
            float wz = __fdiv_rn(z - (bz * gsv - 1.0f), gsv);

            unsigned cx = (unsigned)(ibx + oi);
            unsigned cy = (unsigned)(iby + oj);
            unsigned cz = (unsigned)(ibz + ok);
            unsigned hidx = (cx ^ (cy * 2654435761u) ^ (cz * 805459861u)) & (TSZ - 1u);

            float wc = (oi ? wx : 1.0f - wx) * (oj ? wy : 1.0f - wy) * (ok ? wz : 1.0f - wz);

            const float2* src = tl + hidx;
            float sx[NP], sy[NP];
            #pragma unroll
            for (int p = 0; p < NP; ++p) {
                float2 v = __ldg(src + (size_t)p * (size_t)(NL * (size_t)TSZ));
                sx[p] = wc * v.x;
                sy[p] = wc * v.y;
            }
            #pragma unroll
            for (int m = 1; m < 8; m <<= 1) {
                #pragma unroll
                for (int p = 0; p < NP; ++p) {
                    sx[p] += __shfl_xor_sync(0xffffffffu, sx[p], m);
                    sy[p] += __shfl_xor_sync(0xffffffffu, sy[p], m);
                }
            }
            if (c == 0) {
                float* e = emb_sh + (pbase + q) * (NP * 32) + 2 * l;
                #pragma unroll
                for (int p = 0; p < NP; ++p) {
                    e[p * 32]     = sx[p];
                    e[p * 32 + 1] = sy[p];
                }
            }
        }
    }
    __syncwarp();

    // ---------------- Phase 2: GRU over pieces ----------------
    float h0[4] = {0, 0, 0, 0}, h1[4] = {0, 0, 0, 0};
    float anc[4] = {0, 0, 0, 0};

    for (int p = 0; p < NP; ++p) {
        float ar0[4] = {0,0,0,0}, ar1[4] = {0,0,0,0};
        float az0[4] = {0,0,0,0}, az1[4] = {0,0,0,0};
        float ai0[4] = {0,0,0,0}, ai1[4] = {0,0,0,0};
        float an0[4] = {0,0,0,0}, an1[4] = {0,0,0,0};

        // gi = w_ih @ emb_p  (emb read as float4 broadcast, weights as bf162 pairs)
        #pragma unroll 2
        for (int d4 = 0; d4 < 32; d4 += 4) {
            float4 e4[4];
            #pragma unroll
            for (int q = 0; q < 4; ++q)
                e4[q] = *reinterpret_cast<const float4*>(
                    emb_sh + ((pbase + q) * NP + p) * 32 + d4);
            #pragma unroll
            for (int dd = 0; dd < 4; ++dd) {
                int d = d4 + dd;
                float2 p0 = __bfloat1622float2(wih2[d * 96 + lane]);
                float2 p1 = __bfloat1622float2(wih2[d * 96 + 32 + lane]);
                float2 p2 = __bfloat1622float2(wih2[d * 96 + 64 + lane]);
                #pragma unroll
                for (int q = 0; q < 4; ++q) {
                    float e = (dd == 0) ? e4[q].x : (dd == 1) ? e4[q].y
                            : (dd == 2) ? e4[q].z : e4[q].w;
                    ar0[q] += p0.x * e; ar1[q] += p0.y * e;
                    az0[q] += p1.x * e; az1[q] += p1.y * e;
                    ai0[q] += p2.x * e; ai1[q] += p2.y * e;
                }
            }
        }
        // gh = w_hh @ h
        if (p > 0) {
            #pragma unroll 4
            for (int k = 0; k < 32; ++k) {
                float2 p0 = __bfloat1622float2(whh2[k * 96 + lane]);
                float2 p1 = __bfloat1622float2(whh2[k * 96 + 32 + lane]);
                float2 p2 = __bfloat1622float2(whh2[k * 96 + 64 + lane]);
                #pragma unroll
                for (int q = 0; q < 4; ++q) {
                    float hk = __shfl_sync(0xffffffffu, h0[q], k);
                    ar0[q] += p0.x * hk; ar1[q] += p0.y * hk;
                    az0[q] += p1.x * hk; az1[q] += p1.y * hk;
                    an0[q] += p2.x * hk; an1[q] += p2.y * hk;
                }
            }
            #pragma unroll 4
            for (int k = 0; k < 32; ++k) {
                float2 p0 = __bfloat1622float2(whh2[(k + 32) * 96 + lane]);
                float2 p1 = __bfloat1622float2(whh2[(k + 32) * 96 + 32 + lane]);
                float2 p2 = __bfloat1622float2(whh2[(k + 32) * 96 + 64 + lane]);
                #pragma unroll
                for (int q = 0; q < 4; ++q) {
                    float hk = __shfl_sync(0xffffffffu, h1[q], k);
                    ar0[q] += p0.x * hk; ar1[q] += p0.y * hk;
                    az0[q] += p1.x * hk; az1[q] += p1.y * hk;
                    an0[q] += p2.x * hk; an1[q] += p2.y * hk;
                }
            }
        }
        // gates + h update + delta reduction
        #pragma unroll
        for (int q = 0; q < 4; ++q) {
            float r0 = sigm(ar0[q]), r1 = sigm(ar1[q]);
            float z0 = sigm(az0[q]), z1 = sigm(az1[q]);
            float n0 = tanhf(ai0[q] + r0 * an0[q]);
            float n1 = tanhf(ai1[q] + r1 * an1[q]);
            h0[q] = (1.0f - z0) * n0 + z0 * h0[q];
            h1[q] = (1.0f - z1) * n1 + z1 * h1[q];

            float part = h0[q] * wfc_sh[lane] + h1[q] * wfc_sh[lane + 32];
            #pragma unroll
            for (int m = 16; m >= 1; m >>= 1)
                part += __shfl_xor_sync(0xffffffffu, part, m);
            anc[q] += __fdiv_rn(part * 2.0f, 10.0f);
            if (lane == 0) anc_sh[(pbase + q) * NP + p] = anc[q];
        }
    }
    __syncwarp();

    // ---------------- Phase 3: softmax weights + output ----------------
    #pragma unroll
    for (int q = 0; q < 4; ++q) {
        float t = pt[q].w;
        float lg[NP];
        float mx = -1e30f;
        #pragma unroll
        for (int p = 0; p < NP; ++p) {
            float a = anc_sh[(pbase + q) * NP + p];
            float L = -__fdiv_rn(fabsf(t - a), 100.0f);
            lg[p] = L;
            mx = fmaxf(mx, L);
        }
        float s = 0.0f, o = 0.0f;
        #pragma unroll
        for (int p = 0; p < NP; ++p) {
            float w = __expf(lg[p] - mx);
            s += w;
            o += w * emb_sh[((pbase + q) * NP + p) * 32 + lane];
        }
        out[(size_t)(gpt + q) * 32 + lane] = __fdiv_rn(o, s);
    }
}

extern "C" void kernel_launch(void* const* d_in, const int* in_sizes, int n_in,
                              void* d_out, int out_size)
{
    const float*  xyzt = (const float*)d_in[0];
    const float2* tab  = (const float2*)d_in[1];
    const float*  w_ih = (const float*)d_in[2];
    const float*  w_hh = (const float*)d_in[3];
    const float*  w_fc = (const float*)d_in[4];
    float* out = (float*)d_out;

    ResParams rp;
    double B = exp((log(4096.0) - log(128.0)) / 15.0);
    for (int l = 0; l < NL; ++l) {
        double v = floor(128.0 * pow(B, (double)l));
        rp.gs[l] = 2.0f / (float)v;
    }

    cudaFuncSetAttribute(xyz_tpc_kernel, cudaFuncAttributeMaxDynamicSharedMemorySize, SMEM_BYTES);

    dim3 grid((NPTS + PTS_PER_BLOCK - 1) / PTS_PER_BLOCK);
    xyz_tpc_kernel<<<grid, THREADS, SMEM_BYTES>>>(xyzt, tab, w_ih, w_hh, w_fc, out, rp);
}